// round 1
// baseline (speedup 1.0000x reference)
#include <cuda_runtime.h>

// B = 65536 point clouds, N = 128 points, 3 coords.
// loss = mean( (xc @ R - yc)^2 )  with  R = U @ Vh  (SVD of C = xc^T yc)
//      = [ sum_b ( ||xc_b||^2 + ||yc_b||^2 - 2*nuclear_norm(C_b) ) ] / (B*N*3)
// nuclear_norm(C) = sum sqrt(eig(C^T C))  via closed-form 3x3 symmetric eigensolver.

#define NB 65536
#define NPTS 128
#define WARPS_PER_BLOCK 8
#define THREADS (WARPS_PER_BLOCK * 32)

__device__ double g_accum;

__global__ void kabsch_init() { g_accum = 0.0; }

__global__ void kabsch_finalize(float* out) {
    const double scale = 1.0 / ((double)NB * (double)NPTS * 3.0);
    out[0] = (float)(g_accum * scale);
}

__global__ void __launch_bounds__(THREADS)
kabsch_main(const float* __restrict__ x, const float* __restrict__ y) {
    const int lane  = threadIdx.x & 31;
    const int wib   = threadIdx.x >> 5;                 // warp in block
    const int batch = blockIdx.x * WARPS_PER_BLOCK + wib;

    // batch data: 384 floats = 96 float4, 16B aligned (batch stride 1536B)
    const float4* xb = reinterpret_cast<const float4*>(x) + (size_t)batch * 96;
    const float4* yb = reinterpret_cast<const float4*>(y) + (size_t)batch * 96;

    // Each lane loads 3 float4 = 12 floats = 4 points (x and y).
    float4 a0 = xb[3 * lane + 0];
    float4 a1 = xb[3 * lane + 1];
    float4 a2 = xb[3 * lane + 2];
    float4 b0 = yb[3 * lane + 0];
    float4 b1 = yb[3 * lane + 1];
    float4 b2 = yb[3 * lane + 2];

    // Regroup into 4 (x,y,z) points each.
    float px[4][3] = {{a0.x, a0.y, a0.z}, {a0.w, a1.x, a1.y},
                      {a1.z, a1.w, a2.x}, {a2.y, a2.z, a2.w}};
    float py[4][3] = {{b0.x, b0.y, b0.z}, {b0.w, b1.x, b1.y},
                      {b1.z, b1.w, b2.x}, {b2.y, b2.z, b2.w}};

    // acc layout: [0..2]=sx, [3..5]=sy, [6]=sxx, [7]=syy, [8..16]=C row-major
    float acc[17];
#pragma unroll
    for (int i = 0; i < 17; i++) acc[i] = 0.0f;

#pragma unroll
    for (int p = 0; p < 4; p++) {
#pragma unroll
        for (int j = 0; j < 3; j++) {
            acc[j]     += px[p][j];
            acc[3 + j] += py[p][j];
            acc[6]     += px[p][j] * px[p][j];
            acc[7]     += py[p][j] * py[p][j];
        }
#pragma unroll
        for (int j = 0; j < 3; j++)
#pragma unroll
            for (int k = 0; k < 3; k++)
                acc[8 + 3 * j + k] += px[p][j] * py[p][k];
    }

    // Warp butterfly reduction of all 17 accumulators.
#pragma unroll
    for (int off = 16; off > 0; off >>= 1) {
#pragma unroll
        for (int i = 0; i < 17; i++)
            acc[i] += __shfl_xor_sync(0xffffffffu, acc[i], off);
    }

    __shared__ float warp_loss[WARPS_PER_BLOCK];

    if (lane == 0) {
        const float invN = 1.0f / (float)NPTS;
        float sx0 = acc[0], sx1 = acc[1], sx2 = acc[2];
        float sy0 = acc[3], sy1 = acc[4], sy2 = acc[5];

        // Centered covariance C and centered Frobenius norms.
        float cc[3][3];
        float sxv[3] = {sx0, sx1, sx2};
        float syv[3] = {sy0, sy1, sy2};
#pragma unroll
        for (int j = 0; j < 3; j++)
#pragma unroll
            for (int k = 0; k < 3; k++)
                cc[j][k] = acc[8 + 3 * j + k] - sxv[j] * syv[k] * invN;

        float ax = acc[6] - (sx0 * sx0 + sx1 * sx1 + sx2 * sx2) * invN;
        float ay = acc[7] - (sy0 * sy0 + sy1 * sy1 + sy2 * sy2) * invN;

        // M = C^T C (symmetric PSD)
        float m00 = cc[0][0]*cc[0][0] + cc[1][0]*cc[1][0] + cc[2][0]*cc[2][0];
        float m11 = cc[0][1]*cc[0][1] + cc[1][1]*cc[1][1] + cc[2][1]*cc[2][1];
        float m22 = cc[0][2]*cc[0][2] + cc[1][2]*cc[1][2] + cc[2][2]*cc[2][2];
        float m01 = cc[0][0]*cc[0][1] + cc[1][0]*cc[1][1] + cc[2][0]*cc[2][1];
        float m02 = cc[0][0]*cc[0][2] + cc[1][0]*cc[1][2] + cc[2][0]*cc[2][2];
        float m12 = cc[0][1]*cc[0][2] + cc[1][1]*cc[1][2] + cc[2][1]*cc[2][2];

        // Closed-form eigenvalues of 3x3 symmetric matrix (Smith's trig method)
        float q  = (m00 + m11 + m22) * (1.0f / 3.0f);
        float p1 = m01 * m01 + m02 * m02 + m12 * m12;
        float d0 = m00 - q, d1 = m11 - q, d2 = m22 - q;
        float p2 = d0 * d0 + d1 * d1 + d2 * d2 + 2.0f * p1;
        float p  = sqrtf(fmaxf(p2, 0.0f) * (1.0f / 6.0f));

        float nuclear;
        if (p < 1e-10f) {
            nuclear = 3.0f * sqrtf(fmaxf(q, 0.0f));
        } else {
            float ip  = 1.0f / p;
            float b00 = d0 * ip, b11 = d1 * ip, b22 = d2 * ip;
            float b01 = m01 * ip, b02 = m02 * ip, b12 = m12 * ip;
            float detB = b00 * (b11 * b22 - b12 * b12)
                       - b01 * (b01 * b22 - b12 * b02)
                       + b02 * (b01 * b12 - b11 * b02);
            float r = 0.5f * detB;
            r = fminf(1.0f, fmaxf(-1.0f, r));
            float phi = acosf(r) * (1.0f / 3.0f);
            float e1 = q + 2.0f * p * cosf(phi);
            float e3 = q + 2.0f * p * cosf(phi + 2.09439510239319549f); // +2pi/3
            float e2 = 3.0f * q - e1 - e3;
            nuclear = sqrtf(fmaxf(e1, 0.0f))
                    + sqrtf(fmaxf(e2, 0.0f))
                    + sqrtf(fmaxf(e3, 0.0f));
        }

        warp_loss[wib] = ax + ay - 2.0f * nuclear;
    }

    __syncthreads();

    if (threadIdx.x == 0) {
        double s = 0.0;
#pragma unroll
        for (int i = 0; i < WARPS_PER_BLOCK; i++) s += (double)warp_loss[i];
        atomicAdd(&g_accum, s);
    }
}

extern "C" void kernel_launch(void* const* d_in, const int* in_sizes, int n_in,
                              void* d_out, int out_size) {
    const float* x = (const float*)d_in[0];
    const float* y = (const float*)d_in[1];
    float* out = (float*)d_out;

    kabsch_init<<<1, 1>>>();
    kabsch_main<<<NB / WARPS_PER_BLOCK, THREADS>>>(x, y);
    kabsch_finalize<<<1, 1>>>(out);
}